// round 15
// baseline (speedup 1.0000x reference)
#include <cuda_runtime.h>
#include <cuda_fp16.h>
#include <cuda_bf16.h>
#include <cstdint>

#define NN    50000
#define EE    800000
#define INF   500
#define HDIM  128
#define CDIM  40
#define KSTEPS 10
#define KPAD 512
#define CAP  64      // edge bucket capacity per node (Poisson(16) -> P(>=64) ~ 0)

// Scratch (static __device__ allocations; zero-initialized at load)
__device__ float  g_x[2][(size_t)NN * HDIM];   // fp32 ping-pong x_k
__device__ float  g_hidden[(size_t)NN * HDIM];
__device__ int    g_count[NN];          // zero-init static; gemm2 re-zeroes each call
__device__ int2   g_edges[(size_t)NN * CAP];  // bucketed: (src, norm as float bits)
                                              // unwritten slots stay (0,0): ww=0 -> no-op
__device__ __half g_w1[HDIM * KPAD];    // W1^T fp16, [n][k] (k zero-padded)

#define FMA2(acc, a, b) \
    asm("fma.rn.f32x2 %0, %1, %2, %0;" : "+l"(acc) : "l"(a), "l"(b))

__device__ __forceinline__ void split_fp16(float v, __half& hi, __half& lo) {
    hi = __float2half_rn(v);
    lo = __float2half_rn(v - __half2float(hi));
}

// ---------------------------------------------------------------------------
// K0: conv_w1 (blocks 0..255) ∪ bucket-scatter (blocks 256..) — independent.
// ---------------------------------------------------------------------------
#define CONV_BLOCKS ((HDIM * KPAD + 255) / 256)           // 256
#define SCAT_BLOCKS ((EE / 2 + 255) / 256)                // 1563

__global__ __launch_bounds__(256) void k0_conv_scatter_kernel(
    const float* __restrict__ W1, const int* __restrict__ edge_index,
    const float* __restrict__ norm)
{
    if (blockIdx.x < CONV_BLOCKS) {
        int idx = blockIdx.x * 256 + threadIdx.x;
        if (idx < HDIM * KPAD) {
            int n = idx / KPAD, k = idx % KPAD;
            float v = (k < INF) ? W1[(size_t)k * HDIM + n] : 0.f;
            g_w1[idx] = __float2half_rn(v);
        }
    } else {
        int g = (blockIdx.x - CONV_BLOCKS) * 256 + threadIdx.x;
        if (g < EE / 2) {
            int2 s = *(const int2*)(edge_index + 2 * g);
            int2 d = *(const int2*)(edge_index + EE + 2 * g);
            float2 w = *(const float2*)(norm + 2 * g);
            int p0 = atomicAdd(&g_count[d.x], 1);
            if (p0 < CAP)
                g_edges[(size_t)d.x * CAP + p0] = make_int2(s.x, __float_as_int(w.x));
            int p1 = atomicAdd(&g_count[d.y], 1);
            if (p1 < CAP)
                g_edges[(size_t)d.y * CAP + p1] = make_int2(s.y, __float_as_int(w.y));
        }
    }
}

// ---------------------------------------------------------------------------
// GEMM1 (tensor cores, 2-pass split-fp16: (Ah+Al) @ W1_fp16):
//   x0 = relu(feature @ W1 + b1) -> g_x[0] (fp32); hidden = gamma0 * x0
// ---------------------------------------------------------------------------
__device__ __forceinline__ void mma16816(float c[4], const uint32_t a[4],
                                         uint32_t b0, uint32_t b1) {
    asm volatile(
        "mma.sync.aligned.m16n8k16.row.col.f32.f16.f16.f32 "
        "{%0,%1,%2,%3}, {%4,%5,%6,%7}, {%8,%9}, {%0,%1,%2,%3};"
        : "+f"(c[0]), "+f"(c[1]), "+f"(c[2]), "+f"(c[3])
        : "r"(a[0]), "r"(a[1]), "r"(a[2]), "r"(a[3]), "r"(b0), "r"(b1));
}

__device__ __forceinline__ void ldsm4(uint32_t& r0, uint32_t& r1,
                                      uint32_t& r2, uint32_t& r3, uint32_t addr) {
    asm volatile(
        "ldmatrix.sync.aligned.m8n8.x4.shared.b16 {%0,%1,%2,%3}, [%4];"
        : "=r"(r0), "=r"(r1), "=r"(r2), "=r"(r3) : "r"(addr));
}

#define PADC 40   // smem row length in fp16 (80 bytes) — LDSM conflict-free

__global__ __launch_bounds__(256) void gemm1_tc_kernel(
    const float* __restrict__ A,     // [NN, INF]
    const float* __restrict__ b1,    // [HDIM]
    const float* __restrict__ temp)  // [HDIM, KSTEPS+1]
{
    __shared__ __half Ah[128][PADC];
    __shared__ __half Al[128][PADC];
    __shared__ __half Bs[128][PADC];   // transposed: [n][k]
    __shared__ float sBias[HDIM];
    __shared__ float sG0[HDIM];

    int tid = threadIdx.x;
    int m0 = blockIdx.x * 128;

    if (tid < HDIM) {
        sBias[tid] = b1[tid];
        sG0[tid]   = temp[tid * (KSTEPS + 1)];
    }

    int lane = tid & 31, wid = tid >> 5;
    int g = lane >> 2, tig = lane & 3;
    int wr = wid >> 1, wc = wid & 1;
    int mBase = wr * 32, nBase = wc * 64;

    uint32_t ahBase = (uint32_t)__cvta_generic_to_shared(&Ah[0][0]);
    uint32_t alBase = (uint32_t)__cvta_generic_to_shared(&Al[0][0]);
    uint32_t bBase  = (uint32_t)__cvta_generic_to_shared(&Bs[0][0]);

    int aRow = mBase + (lane & 7) + ((lane >> 3) & 1) * 8;
    uint32_t aOff = (uint32_t)(aRow * (PADC * 2) + ((lane >> 4) & 1) * 16);
    int bRow = nBase + (lane & 7) + ((lane >> 4) & 1) * 8;
    uint32_t bOff = (uint32_t)(bRow * (PADC * 2) + ((lane >> 3) & 1) * 16);

    float c[2][8][4];
#pragma unroll
    for (int mt = 0; mt < 2; ++mt)
#pragma unroll
        for (int nt = 0; nt < 8; ++nt)
#pragma unroll
            for (int q = 0; q < 4; ++q) c[mt][nt][q] = 0.f;

    for (int k0 = 0; k0 < 512; k0 += 32) {
        // ---- A tile: 128x32 fp32 -> split fp16, STS.64 ----
#pragma unroll
        for (int i = 0; i < 4; ++i) {
            int idx = tid + 256 * i;
            int row = idx >> 3;
            int c4  = (idx & 7) * 4;
            int grow = m0 + row;
            int gk = k0 + c4;
            float4 v = make_float4(0.f, 0.f, 0.f, 0.f);
            if (grow < NN && gk + 4 <= INF)
                v = *(const float4*)(A + (size_t)grow * INF + gk);
            __half h[4], l[4];
            split_fp16(v.x, h[0], l[0]);
            split_fp16(v.y, h[1], l[1]);
            split_fp16(v.z, h[2], l[2]);
            split_fp16(v.w, h[3], l[3]);
            *(uint2*)&Ah[row][c4] = *(uint2*)h;
            *(uint2*)&Al[row][c4] = *(uint2*)l;
        }
        // ---- B tile: pure copy of preconverted W1^T (128x32 fp16) ----
        {
            int idx = tid;                 // 512 uint4 slots, 2 per thread
#pragma unroll
            for (int i = 0; i < 2; ++i, idx += 256) {
                int n   = idx >> 2;
                int kr8 = (idx & 3) * 8;
                *(uint4*)&Bs[n][kr8] = *(const uint4*)&g_w1[n * KPAD + k0 + kr8];
            }
        }
        __syncthreads();

#pragma unroll
        for (int kk = 0; kk < 32; kk += 16) {
            uint32_t AH[2][4], AL[2][4];
#pragma unroll
            for (int mt = 0; mt < 2; ++mt) {
                uint32_t off = aOff + (uint32_t)(mt * 16 * PADC * 2 + kk * 2);
                ldsm4(AH[mt][0], AH[mt][1], AH[mt][2], AH[mt][3], ahBase + off);
                ldsm4(AL[mt][0], AL[mt][1], AL[mt][2], AL[mt][3], alBase + off);
            }
#pragma unroll
            for (int np = 0; np < 4; ++np) {
                uint32_t off = bOff + (uint32_t)(np * 16 * PADC * 2 + kk * 2);
                uint32_t BH[4];
                ldsm4(BH[0], BH[1], BH[2], BH[3], bBase + off);
#pragma unroll
                for (int mt = 0; mt < 2; ++mt) {
                    mma16816(c[mt][2 * np],     AH[mt], BH[0], BH[1]);
                    mma16816(c[mt][2 * np],     AL[mt], BH[0], BH[1]);
                    mma16816(c[mt][2 * np + 1], AH[mt], BH[2], BH[3]);
                    mma16816(c[mt][2 * np + 1], AL[mt], BH[2], BH[3]);
                }
            }
        }
        __syncthreads();
    }

    // epilogue: bias+relu -> fp32 x0 ; hidden = gamma0 * x0
#pragma unroll
    for (int mt = 0; mt < 2; ++mt) {
#pragma unroll
        for (int nt = 0; nt < 8; ++nt) {
            int col = nBase + nt * 8 + 2 * tig;
            float bb0 = sBias[col], bb1 = sBias[col + 1];
            float g0 = sG0[col], g1 = sG0[col + 1];
#pragma unroll
            for (int rh = 0; rh < 2; ++rh) {
                int row = m0 + mBase + mt * 16 + g + rh * 8;
                if (row >= NN) continue;
                float v0 = fmaxf(c[mt][nt][rh * 2 + 0] + bb0, 0.f);
                float v1 = fmaxf(c[mt][nt][rh * 2 + 1] + bb1, 0.f);
                *(float2*)(&g_x[0][(size_t)row * HDIM + col]) = make_float2(v0, v1);
                *(float2*)(g_hidden + (size_t)row * HDIM + col) =
                    make_float2(v0 * g0, v1 * g1);
            }
        }
    }
}

// ---------------------------------------------------------------------------
// Propagation step k (fp32): half-warp per node; lane = 8 channels (2 float4).
// x_k = sum_e w[e] * x_{k-1}[src[e]] ; hidden += gamma_k * x_k (inline).
// Buckets zero-padded: ww=0 slots contribute nothing.
// ---------------------------------------------------------------------------
__global__ __launch_bounds__(256) void prop_step_kernel(
    int k, const float* __restrict__ temp)
{
    __shared__ float sG[HDIM];
    int tid = threadIdx.x;
    if (tid < HDIM) sG[tid] = temp[tid * (KSTEPS + 1) + k];
    __syncthreads();

    const float* __restrict__ xin  = g_x[(k - 1) & 1];
    float* __restrict__       xout = g_x[k & 1];

    int hw = (blockIdx.x * blockDim.x + tid) >> 4;   // node
    int cg = tid & 15;                               // channel group
    if (hw >= NN) return;

    int deg = g_count[hw];
    if (deg > CAP) deg = CAP;
    int deg2 = (deg + 1) & ~1;                 // zero-padded to even
    const int4* __restrict__ e4 = (const int4*)(g_edges + (size_t)hw * CAP);

    float a0 = 0.f, a1 = 0.f, a2 = 0.f, a3 = 0.f;
    float a4 = 0.f, a5 = 0.f, a6 = 0.f, a7 = 0.f;
    const float4* __restrict__ x4 = (const float4*)xin;
    int c2 = cg * 2;

#pragma unroll 4
    for (int e = 0; e < deg2; e += 2) {
        int4 p = __ldg(&e4[e >> 1]);           // edges e (x,y), e+1 (z,w)
        float w0 = __int_as_float(p.y);
        float w1 = __int_as_float(p.w);
        float4 ua = __ldg(x4 + ((size_t)p.x * 32 + c2));
        float4 ub = __ldg(x4 + ((size_t)p.x * 32 + c2 + 1));
        float4 va = __ldg(x4 + ((size_t)p.z * 32 + c2));
        float4 vb = __ldg(x4 + ((size_t)p.z * 32 + c2 + 1));

        a0 += w0 * ua.x;  a1 += w0 * ua.y;
        a2 += w0 * ua.z;  a3 += w0 * ua.w;
        a4 += w0 * ub.x;  a5 += w0 * ub.y;
        a6 += w0 * ub.z;  a7 += w0 * ub.w;

        a0 += w1 * va.x;  a1 += w1 * va.y;
        a2 += w1 * va.z;  a3 += w1 * va.w;
        a4 += w1 * vb.x;  a5 += w1 * vb.y;
        a6 += w1 * vb.z;  a7 += w1 * vb.w;
    }

    size_t ob = (size_t)hw * 32 + c2;
    ((float4*)xout)[ob]     = make_float4(a0, a1, a2, a3);
    ((float4*)xout)[ob + 1] = make_float4(a4, a5, a6, a7);

    // hidden += gamma_k * x_k (inline)
    int c0 = cg * 8;
    float4 G0 = *(float4*)&sG[c0];
    float4 G1 = *(float4*)&sG[c0 + 4];
    float4* h4 = (float4*)g_hidden;
    float4 h0 = h4[ob], h1 = h4[ob + 1];
    h0.x += G0.x * a0;  h0.y += G0.y * a1;
    h0.z += G0.z * a2;  h0.w += G0.w * a3;
    h1.x += G1.x * a4;  h1.y += G1.y * a5;
    h1.z += G1.z * a6;  h1.w += G1.w * a7;
    h4[ob]     = h0;
    h4[ob + 1] = h1;
}

// ---------------------------------------------------------------------------
// GEMM2: out = hidden @ W2 + b2 (also re-zeroes g_count for next call)
// ---------------------------------------------------------------------------
#define G2_T 128
#define G2_NPB (G2_T * 4)   // 512 nodes per block

__global__ __launch_bounds__(G2_T) void gemm2_kernel(
    const float* __restrict__ W2,   // [HDIM, CDIM]
    const float* __restrict__ b2,   // [CDIM]
    float* __restrict__ out)        // [NN, CDIM]
{
    __shared__ float sW[HDIM * CDIM];
    __shared__ float sb[CDIM];
    for (int i = threadIdx.x; i < HDIM * CDIM; i += G2_T) sW[i] = W2[i];
    if (threadIdx.x < CDIM) sb[threadIdx.x] = b2[threadIdx.x];
    __syncthreads();

    int nodeBase = blockIdx.x * G2_NPB + threadIdx.x;
    int node[4];
    bool ok[4];
#pragma unroll
    for (int j = 0; j < 4; ++j) {
        node[j] = nodeBase + j * G2_T;
        ok[j] = node[j] < NN;
        if (ok[j]) g_count[node[j]] = 0;   // reset bucket cursor for next call
    }

    unsigned long long acc[4][CDIM / 2];
#pragma unroll
    for (int c = 0; c < CDIM / 2; ++c) {
        unsigned long long b = *(const unsigned long long*)(sb + 2 * c);
#pragma unroll
        for (int j = 0; j < 4; ++j) acc[j][c] = b;
    }

    for (int h4 = 0; h4 < HDIM / 4; ++h4) {
        float4 hv[4];
#pragma unroll
        for (int j = 0; j < 4; ++j)
            hv[j] = ok[j] ? __ldg((const float4*)(g_hidden + (size_t)node[j] * HDIM) + h4)
                          : make_float4(0.f, 0.f, 0.f, 0.f);
#pragma unroll
        for (int hh = 0; hh < 4; ++hh) {
            int h = h4 * 4 + hh;
            const unsigned long long* wrow =
                (const unsigned long long*)(sW + h * CDIM);
            float hs[4] = {
                hh == 0 ? hv[0].x : hh == 1 ? hv[0].y : hh == 2 ? hv[0].z : hv[0].w,
                hh == 0 ? hv[1].x : hh == 1 ? hv[1].y : hh == 2 ? hv[1].z : hv[1].w,
                hh == 0 ? hv[2].x : hh == 1 ? hv[2].y : hh == 2 ? hv[2].z : hv[2].w,
                hh == 0 ? hv[3].x : hh == 1 ? hv[3].y : hh == 2 ? hv[3].z : hv[3].w};
            unsigned long long hp[4];
#pragma unroll
            for (int j = 0; j < 4; ++j) {
                uint32_t hb = __float_as_uint(hs[j]);
                asm("mov.b64 %0, {%1,%1};" : "=l"(hp[j]) : "r"(hb));
            }
#pragma unroll
            for (int c = 0; c < CDIM / 2; ++c) {
                unsigned long long wp = wrow[c];
                FMA2(acc[0][c], hp[0], wp);
                FMA2(acc[1][c], hp[1], wp);
                FMA2(acc[2][c], hp[2], wp);
                FMA2(acc[3][c], hp[3], wp);
            }
        }
    }

#pragma unroll
    for (int j = 0; j < 4; ++j) {
        if (!ok[j]) continue;
        unsigned long long* o = (unsigned long long*)(out + (size_t)node[j] * CDIM);
#pragma unroll
        for (int c = 0; c < CDIM / 2; ++c) o[c] = acc[j][c];
    }
}

// ---------------------------------------------------------------------------
extern "C" void kernel_launch(void* const* d_in, const int* in_sizes, int n_in,
                              void* d_out, int out_size)
{
    const float* feature    = (const float*)d_in[0];
    const float* W1         = (const float*)d_in[1];
    const float* b1         = (const float*)d_in[2];
    const float* W2         = (const float*)d_in[3];
    const float* b2         = (const float*)d_in[4];
    const float* temp       = (const float*)d_in[5];
    const float* norm       = (const float*)d_in[6];
    const int*   edge_index = (const int*)d_in[7];
    float* out = (float*)d_out;

    // K0: W1 preconvert ∪ bucket scatter (no hist, no scan)
    k0_conv_scatter_kernel<<<CONV_BLOCKS + SCAT_BLOCKS, 256>>>(W1, edge_index, norm);

    // lin1 + relu (tensor cores, 2-pass split-fp16); hidden = gamma0 * x0
    gemm1_tc_kernel<<<(NN + 127) / 128, 256>>>(feature, b1, temp);

    // K propagation steps (fp32 gather + FFMA, inline hidden accumulation)
    int prop_blocks = (NN * 16 + 255) / 256;
    for (int k = 1; k <= KSTEPS; ++k)
        prop_step_kernel<<<prop_blocks, 256>>>(k, temp);

    // lin2 (also re-zeroes bucket cursors)
    gemm2_kernel<<<(NN + G2_NPB - 1) / G2_NPB, G2_T>>>(W2, b2, out);
}

// round 16
// speedup vs baseline: 1.5427x; 1.5427x over previous
#include <cuda_runtime.h>
#include <cuda_fp16.h>
#include <cuda_bf16.h>
#include <cstdint>

#define NN    50000
#define EE    800000
#define INF   500
#define HDIM  128
#define CDIM  40
#define KSTEPS 10
#define KPAD 512
#define CAP  64      // edge bucket capacity per node (Poisson(16) -> P(>=64) ~ 0)

// Scratch (static __device__ allocations; zero-initialized at load)
__device__ __half g_xbuf[KSTEPS + 1][(size_t)NN * HDIM];  // x_k / 16^k
__device__ float  g_hidden[(size_t)NN * HDIM];
__device__ int    g_count[NN];          // zero-init static; combine re-zeroes each call
__device__ int2   g_edges[(size_t)NN * CAP];  // bucketed: (src, norm/16 as float bits)
                                              // unwritten slots stay (0,0): ww=0 -> no-op
__device__ __half g_w1[HDIM * KPAD];    // W1^T fp16, [n][k] (k zero-padded)

#define FMA2(acc, a, b) \
    asm("fma.rn.f32x2 %0, %1, %2, %0;" : "+l"(acc) : "l"(a), "l"(b))

__device__ __forceinline__ void split_fp16(float v, __half& hi, __half& lo) {
    hi = __float2half_rn(v);
    lo = __float2half_rn(v - __half2float(hi));
}

// ---------------------------------------------------------------------------
// K0: conv_w1 (blocks 0..255) ∪ bucket-scatter (blocks 256..) — independent.
// ---------------------------------------------------------------------------
#define CONV_BLOCKS ((HDIM * KPAD + 255) / 256)           // 256
#define SCAT_BLOCKS ((EE / 2 + 255) / 256)                // 1563

__global__ __launch_bounds__(256) void k0_conv_scatter_kernel(
    const float* __restrict__ W1, const int* __restrict__ edge_index,
    const float* __restrict__ norm)
{
    if (blockIdx.x < CONV_BLOCKS) {
        int idx = blockIdx.x * 256 + threadIdx.x;
        if (idx < HDIM * KPAD) {
            int n = idx / KPAD, k = idx % KPAD;
            float v = (k < INF) ? W1[(size_t)k * HDIM + n] : 0.f;
            g_w1[idx] = __float2half_rn(v);
        }
    } else {
        int g = (blockIdx.x - CONV_BLOCKS) * 256 + threadIdx.x;
        if (g < EE / 2) {
            int2 s = *(const int2*)(edge_index + 2 * g);
            int2 d = *(const int2*)(edge_index + EE + 2 * g);
            float2 w = *(const float2*)(norm + 2 * g);
            int p0 = atomicAdd(&g_count[d.x], 1);
            if (p0 < CAP)
                g_edges[(size_t)d.x * CAP + p0] =
                    make_int2(s.x, __float_as_int(w.x * 0.0625f));
            int p1 = atomicAdd(&g_count[d.y], 1);
            if (p1 < CAP)
                g_edges[(size_t)d.y * CAP + p1] =
                    make_int2(s.y, __float_as_int(w.y * 0.0625f));
        }
    }
}

// ---------------------------------------------------------------------------
// GEMM1 (tensor cores, 2-pass split-fp16, software-pipelined A loads):
//   x0 = relu(feature @ W1 + b1) -> g_xbuf[0] (fp16)
// ---------------------------------------------------------------------------
__device__ __forceinline__ void mma16816(float c[4], const uint32_t a[4],
                                         uint32_t b0, uint32_t b1) {
    asm volatile(
        "mma.sync.aligned.m16n8k16.row.col.f32.f16.f16.f32 "
        "{%0,%1,%2,%3}, {%4,%5,%6,%7}, {%8,%9}, {%0,%1,%2,%3};"
        : "+f"(c[0]), "+f"(c[1]), "+f"(c[2]), "+f"(c[3])
        : "r"(a[0]), "r"(a[1]), "r"(a[2]), "r"(a[3]), "r"(b0), "r"(b1));
}

__device__ __forceinline__ void ldsm4(uint32_t& r0, uint32_t& r1,
                                      uint32_t& r2, uint32_t& r3, uint32_t addr) {
    asm volatile(
        "ldmatrix.sync.aligned.m8n8.x4.shared.b16 {%0,%1,%2,%3}, [%4];"
        : "=r"(r0), "=r"(r1), "=r"(r2), "=r"(r3) : "r"(addr));
}

#define PADC 40   // smem row length in fp16 (80 bytes) — LDSM conflict-free

__global__ __launch_bounds__(256, 2) void gemm1_tc_kernel(
    const float* __restrict__ A,     // [NN, INF]
    const float* __restrict__ b1)    // [HDIM]
{
    __shared__ __half Ah[128][PADC];
    __shared__ __half Al[128][PADC];
    __shared__ __half Bs[128][PADC];   // transposed: [n][k]
    __shared__ float sBias[HDIM];

    int tid = threadIdx.x;
    int m0 = blockIdx.x * 128;

    if (tid < HDIM) sBias[tid] = b1[tid];

    int lane = tid & 31, wid = tid >> 5;
    int g = lane >> 2, tig = lane & 3;
    int wr = wid >> 1, wc = wid & 1;
    int mBase = wr * 32, nBase = wc * 64;

    uint32_t ahBase = (uint32_t)__cvta_generic_to_shared(&Ah[0][0]);
    uint32_t alBase = (uint32_t)__cvta_generic_to_shared(&Al[0][0]);
    uint32_t bBase  = (uint32_t)__cvta_generic_to_shared(&Bs[0][0]);

    int aRow = mBase + (lane & 7) + ((lane >> 3) & 1) * 8;
    uint32_t aOff = (uint32_t)(aRow * (PADC * 2) + ((lane >> 4) & 1) * 16);
    int bRow = nBase + (lane & 7) + ((lane >> 4) & 1) * 8;
    uint32_t bOff = (uint32_t)(bRow * (PADC * 2) + ((lane >> 3) & 1) * 16);

    // thread's fixed A-tile slots
    int sRow = tid >> 3;              // 0..31 base row (stride 32 over i)
    int sC4  = (tid & 7) * 4;         // k offset within tile

    float c[2][8][4];
#pragma unroll
    for (int mt = 0; mt < 2; ++mt)
#pragma unroll
        for (int nt = 0; nt < 8; ++nt)
#pragma unroll
            for (int q = 0; q < 4; ++q) c[mt][nt][q] = 0.f;

    // ---- prologue: load A tile for k0=0 into registers ----
    float4 vA[4];
#pragma unroll
    for (int i = 0; i < 4; ++i) {
        int row = sRow + 32 * i;
        int grow = m0 + row;
        int gk = sC4;
        vA[i] = make_float4(0.f, 0.f, 0.f, 0.f);
        if (grow < NN && gk + 4 <= INF)
            vA[i] = *(const float4*)(A + (size_t)grow * INF + gk);
    }

    for (int k0 = 0; k0 < 512; k0 += 32) {
        // ---- store prefetched A regs -> split fp16 smem ----
#pragma unroll
        for (int i = 0; i < 4; ++i) {
            int row = sRow + 32 * i;
            __half h[4], l[4];
            split_fp16(vA[i].x, h[0], l[0]);
            split_fp16(vA[i].y, h[1], l[1]);
            split_fp16(vA[i].z, h[2], l[2]);
            split_fp16(vA[i].w, h[3], l[3]);
            *(uint2*)&Ah[row][sC4] = *(uint2*)h;
            *(uint2*)&Al[row][sC4] = *(uint2*)l;
        }
        // ---- B tile: pure copy of preconverted W1^T (128x32 fp16) ----
        {
            int idx = tid;                 // 512 uint4 slots, 2 per thread
#pragma unroll
            for (int i = 0; i < 2; ++i, idx += 256) {
                int n   = idx >> 2;
                int kr8 = (idx & 3) * 8;
                *(uint4*)&Bs[n][kr8] = *(const uint4*)&g_w1[n * KPAD + k0 + kr8];
            }
        }
        __syncthreads();

        // ---- prefetch next A tile (overlaps the MMA phase below) ----
        if (k0 + 32 < 512) {
            int gkn = k0 + 32 + sC4;
#pragma unroll
            for (int i = 0; i < 4; ++i) {
                int row = sRow + 32 * i;
                int grow = m0 + row;
                vA[i] = make_float4(0.f, 0.f, 0.f, 0.f);
                if (grow < NN && gkn + 4 <= INF)
                    vA[i] = *(const float4*)(A + (size_t)grow * INF + gkn);
            }
        }

#pragma unroll
        for (int kk = 0; kk < 32; kk += 16) {
            uint32_t AH[2][4], AL[2][4];
#pragma unroll
            for (int mt = 0; mt < 2; ++mt) {
                uint32_t off = aOff + (uint32_t)(mt * 16 * PADC * 2 + kk * 2);
                ldsm4(AH[mt][0], AH[mt][1], AH[mt][2], AH[mt][3], ahBase + off);
                ldsm4(AL[mt][0], AL[mt][1], AL[mt][2], AL[mt][3], alBase + off);
            }
#pragma unroll
            for (int np = 0; np < 4; ++np) {
                uint32_t off = bOff + (uint32_t)(np * 16 * PADC * 2 + kk * 2);
                uint32_t BH[4];
                ldsm4(BH[0], BH[1], BH[2], BH[3], bBase + off);
#pragma unroll
                for (int mt = 0; mt < 2; ++mt) {
                    mma16816(c[mt][2 * np],     AH[mt], BH[0], BH[1]);
                    mma16816(c[mt][2 * np],     AL[mt], BH[0], BH[1]);
                    mma16816(c[mt][2 * np + 1], AH[mt], BH[2], BH[3]);
                    mma16816(c[mt][2 * np + 1], AL[mt], BH[2], BH[3]);
                }
            }
        }
        __syncthreads();
    }

    // epilogue: bias+relu -> fp16 x0
#pragma unroll
    for (int mt = 0; mt < 2; ++mt) {
#pragma unroll
        for (int nt = 0; nt < 8; ++nt) {
            int col = nBase + nt * 8 + 2 * tig;
            float bb0 = sBias[col], bb1 = sBias[col + 1];
#pragma unroll
            for (int rh = 0; rh < 2; ++rh) {
                int row = m0 + mBase + mt * 16 + g + rh * 8;
                if (row >= NN) continue;
                float v0 = fmaxf(c[mt][nt][rh * 2 + 0] + bb0, 0.f);
                float v1 = fmaxf(c[mt][nt][rh * 2 + 1] + bb1, 0.f);
                *(__half2*)(&g_xbuf[0][(size_t)row * HDIM + col]) =
                    __floats2half2_rn(v0, v1);
            }
        }
    }
}

// ---------------------------------------------------------------------------
// Propagation step k: half-warp per node; lane = 8 channels (uint4).
// fp32 FFMA accumulation, int4 edge pairs + unroll 4 for MLP~8. (R14 verbatim)
// ---------------------------------------------------------------------------
__global__ __launch_bounds__(256) void prop_step_kernel(int k)
{
    const __half* __restrict__ xin  = g_xbuf[k - 1];
    __half* __restrict__       xout = g_xbuf[k];

    int hw = (blockIdx.x * blockDim.x + threadIdx.x) >> 4;   // node
    int cg = threadIdx.x & 15;                               // channel group
    if (hw >= NN) return;

    int deg = g_count[hw];
    if (deg > CAP) deg = CAP;
    int deg2 = (deg + 1) & ~1;                 // zero-padded to even
    const int4* __restrict__ e4 = (const int4*)(g_edges + (size_t)hw * CAP);

    float a0 = 0.f, a1 = 0.f, a2 = 0.f, a3 = 0.f;
    float a4 = 0.f, a5 = 0.f, a6 = 0.f, a7 = 0.f;
    const uint4* xin16 = (const uint4*)xin;

#pragma unroll 4
    for (int e = 0; e < deg2; e += 2) {
        int4 p = __ldg(&e4[e >> 1]);           // edges e (x,y), e+1 (z,w)
        float w0 = __int_as_float(p.y);
        float w1 = __int_as_float(p.w);
        uint4 u0 = __ldg(xin16 + ((size_t)p.x * 16 + cg));
        uint4 u1 = __ldg(xin16 + ((size_t)p.z * 16 + cg));

        float2 f;
        f = __half22float2(*(__half2*)&u0.x); a0 += w0 * f.x; a1 += w0 * f.y;
        f = __half22float2(*(__half2*)&u0.y); a2 += w0 * f.x; a3 += w0 * f.y;
        f = __half22float2(*(__half2*)&u0.z); a4 += w0 * f.x; a5 += w0 * f.y;
        f = __half22float2(*(__half2*)&u0.w); a6 += w0 * f.x; a7 += w0 * f.y;

        f = __half22float2(*(__half2*)&u1.x); a0 += w1 * f.x; a1 += w1 * f.y;
        f = __half22float2(*(__half2*)&u1.y); a2 += w1 * f.x; a3 += w1 * f.y;
        f = __half22float2(*(__half2*)&u1.z); a4 += w1 * f.x; a5 += w1 * f.y;
        f = __half22float2(*(__half2*)&u1.w); a6 += w1 * f.x; a7 += w1 * f.y;
    }

    uint4 o;
    *(__half2*)&o.x = __floats2half2_rn(a0, a1);
    *(__half2*)&o.y = __floats2half2_rn(a2, a3);
    *(__half2*)&o.z = __floats2half2_rn(a4, a5);
    *(__half2*)&o.w = __floats2half2_rn(a6, a7);
    ((uint4*)xout)[(size_t)hw * 16 + cg] = o;
}

// ---------------------------------------------------------------------------
// Combine: hidden[n,c] = sum_k temp[c,k] * 16^k * g_xbuf[k][n,c]
// Also re-zeroes g_count for the next call (deterministic invariant).
// ---------------------------------------------------------------------------
__global__ __launch_bounds__(256) void combine_kernel(const float* __restrict__ temp)
{
    __shared__ float sG[HDIM][KSTEPS + 1];
    int t = threadIdx.x;
    for (int idx = t; idx < HDIM * (KSTEPS + 1); idx += 256) {
        int c = idx / (KSTEPS + 1), k = idx % (KSTEPS + 1);
        sG[c][k] = temp[idx] * (float)(1u << (2 * k)) * (float)(1u << (2 * k));  // 16^k
    }
    __syncthreads();

    int cg = t & 15;
    float G[8][KSTEPS + 1];
#pragma unroll
    for (int j = 0; j < 8; ++j)
#pragma unroll
        for (int k = 0; k <= KSTEPS; ++k)
            G[j][k] = sG[cg * 8 + j][k];

    int stride = gridDim.x * blockDim.x;
    for (int idx = blockIdx.x * 256 + t; idx < NN * 16; idx += stride) {
        int n = idx >> 4;
        if (cg == 0) g_count[n] = 0;     // reset bucket cursor for next call
        float acc[8] = {0.f, 0.f, 0.f, 0.f, 0.f, 0.f, 0.f, 0.f};
#pragma unroll
        for (int k = 0; k <= KSTEPS; ++k) {
            uint4 u = __ldg((const uint4*)&g_xbuf[k][0] + ((size_t)n * 16 + cg));
            float2 f0 = __half22float2(*(__half2*)&u.x);
            float2 f1 = __half22float2(*(__half2*)&u.y);
            float2 f2 = __half22float2(*(__half2*)&u.z);
            float2 f3 = __half22float2(*(__half2*)&u.w);
            acc[0] += G[0][k] * f0.x;  acc[1] += G[1][k] * f0.y;
            acc[2] += G[2][k] * f1.x;  acc[3] += G[3][k] * f1.y;
            acc[4] += G[4][k] * f2.x;  acc[5] += G[5][k] * f2.y;
            acc[6] += G[6][k] * f3.x;  acc[7] += G[7][k] * f3.y;
        }
        float4* o = (float4*)(g_hidden + (size_t)n * HDIM + cg * 8);
        o[0] = make_float4(acc[0], acc[1], acc[2], acc[3]);
        o[1] = make_float4(acc[4], acc[5], acc[6], acc[7]);
    }
}

// ---------------------------------------------------------------------------
// GEMM2: out = hidden @ W2 + b2
// ---------------------------------------------------------------------------
#define G2_T 128
#define G2_NPB (G2_T * 4)   // 512 nodes per block

__global__ __launch_bounds__(G2_T) void gemm2_kernel(
    const float* __restrict__ W2,   // [HDIM, CDIM]
    const float* __restrict__ b2,   // [CDIM]
    float* __restrict__ out)        // [NN, CDIM]
{
    __shared__ float sW[HDIM * CDIM];
    __shared__ float sb[CDIM];
    for (int i = threadIdx.x; i < HDIM * CDIM; i += G2_T) sW[i] = W2[i];
    if (threadIdx.x < CDIM) sb[threadIdx.x] = b2[threadIdx.x];
    __syncthreads();

    int nodeBase = blockIdx.x * G2_NPB + threadIdx.x;
    int node[4];
    bool ok[4];
#pragma unroll
    for (int j = 0; j < 4; ++j) {
        node[j] = nodeBase + j * G2_T;
        ok[j] = node[j] < NN;
    }

    unsigned long long acc[4][CDIM / 2];
#pragma unroll
    for (int c = 0; c < CDIM / 2; ++c) {
        unsigned long long b = *(const unsigned long long*)(sb + 2 * c);
#pragma unroll
        for (int j = 0; j < 4; ++j) acc[j][c] = b;
    }

    for (int h4 = 0; h4 < HDIM / 4; ++h4) {
        float4 hv[4];
#pragma unroll
        for (int j = 0; j < 4; ++j)
            hv[j] = ok[j] ? __ldg((const float4*)(g_hidden + (size_t)node[j] * HDIM) + h4)
                          : make_float4(0.f, 0.f, 0.f, 0.f);
#pragma unroll
        for (int hh = 0; hh < 4; ++hh) {
            int h = h4 * 4 + hh;
            const unsigned long long* wrow =
                (const unsigned long long*)(sW + h * CDIM);
            float hs[4] = {
                hh == 0 ? hv[0].x : hh == 1 ? hv[0].y : hh == 2 ? hv[0].z : hv[0].w,
                hh == 0 ? hv[1].x : hh == 1 ? hv[1].y : hh == 2 ? hv[1].z : hv[1].w,
                hh == 0 ? hv[2].x : hh == 1 ? hv[2].y : hh == 2 ? hv[2].z : hv[2].w,
                hh == 0 ? hv[3].x : hh == 1 ? hv[3].y : hh == 2 ? hv[3].z : hv[3].w};
            unsigned long long hp[4];
#pragma unroll
            for (int j = 0; j < 4; ++j) {
                uint32_t hb = __float_as_uint(hs[j]);
                asm("mov.b64 %0, {%1,%1};" : "=l"(hp[j]) : "r"(hb));
            }
#pragma unroll
            for (int c = 0; c < CDIM / 2; ++c) {
                unsigned long long wp = wrow[c];
                FMA2(acc[0][c], hp[0], wp);
                FMA2(acc[1][c], hp[1], wp);
                FMA2(acc[2][c], hp[2], wp);
                FMA2(acc[3][c], hp[3], wp);
            }
        }
    }

#pragma unroll
    for (int j = 0; j < 4; ++j) {
        if (!ok[j]) continue;
        unsigned long long* o = (unsigned long long*)(out + (size_t)node[j] * CDIM);
#pragma unroll
        for (int c = 0; c < CDIM / 2; ++c) o[c] = acc[j][c];
    }
}

// ---------------------------------------------------------------------------
extern "C" void kernel_launch(void* const* d_in, const int* in_sizes, int n_in,
                              void* d_out, int out_size)
{
    const float* feature    = (const float*)d_in[0];
    const float* W1         = (const float*)d_in[1];
    const float* b1         = (const float*)d_in[2];
    const float* W2         = (const float*)d_in[3];
    const float* b2         = (const float*)d_in[4];
    const float* temp       = (const float*)d_in[5];
    const float* norm       = (const float*)d_in[6];
    const int*   edge_index = (const int*)d_in[7];
    float* out = (float*)d_out;

    // K0: W1 preconvert ∪ bucket scatter (no hist, no scan)
    k0_conv_scatter_kernel<<<CONV_BLOCKS + SCAT_BLOCKS, 256>>>(W1, edge_index, norm);

    // lin1 + relu (tensor cores, 2-pass split-fp16, pipelined A loads)
    gemm1_tc_kernel<<<(NN + 127) / 128, 256>>>(feature, b1);

    // K propagation steps (fp32 FFMA accumulate, int4 edge pairs, MLP~8)
    int prop_blocks = (NN * 16 + 255) / 256;
    for (int k = 1; k <= KSTEPS; ++k)
        prop_step_kernel<<<prop_blocks, 256>>>(k);

    // hidden = sum_k gamma_k 16^k x_k (also re-zeroes bucket cursors)
    combine_kernel<<<256, 256>>>(temp);

    // lin2
    gemm2_kernel<<<(NN + G2_NPB - 1) / G2_NPB, G2_T>>>(W2, b2, out);
}